// round 14
// baseline (speedup 1.0000x reference)
#include <cuda_runtime.h>
#include <cuda_bf16.h>
#include <cstdint>

#define NN 100000
#define EE 800000
#define DD 96
#define ELLW 64
#define AP 56

// ---------------- device scratch (allocation-free) ----------------
__device__ float g_h[NN * DD];
__device__ float g_mid[NN * DD];
__device__ float g_alpha_s[NN];
__device__ float g_alpha_d[NN];
__device__ int   g_ell[NN * ELLW];
__device__ int   g_counts[NN];
__device__ uint32_t g_wh[2][96 * AP];
__device__ uint32_t g_wl[2][96 * AP];

__device__ __forceinline__ uint16_t bfbits(float x) {
    __nv_bfloat16 b = __float2bfloat16(x);
    return *reinterpret_cast<uint16_t*>(&b);
}
__device__ __forceinline__ float bfval(uint16_t u) {
    __nv_bfloat16 b = *reinterpret_cast<__nv_bfloat16*>(&u);
    return __bfloat162float(b);
}
__device__ __forceinline__ int permj(int j) {
    return (j < 4) ? 2 * j : 2 * (j - 4) + 1;
}

// ---------------- ELL build ----------------
__global__ void k_build(const int* __restrict__ ei) {
    __shared__ int s_is64;
    if (threadIdx.x == 0)
        s_is64 = (ei[1] == 0 && ei[3] == 0 && ei[5] == 0) ? 1 : 0;
    __syncthreads();
    int e = blockIdx.x * blockDim.x + threadIdx.x;
    if (e >= EE) return;
    int s, d;
    if (s_is64) { s = ei[2 * e]; d = ei[2 * (EE + e)]; }
    else        { s = ei[e];     d = ei[EE + e]; }
    int slot = atomicAdd(&g_counts[s], 1);
    if (slot < ELLW) g_ell[s * ELLW + slot] = d;
}

// ---------------- W prep ----------------
__global__ void k_wprep(const float* __restrict__ W1, const float* __restrict__ W2) {
    int ly = blockIdx.x;
    const float* W = ly ? W2 : W1;
    uint16_t* Bh16 = (uint16_t*)g_wh[ly];
    uint16_t* Bl16 = (uint16_t*)g_wl[ly];
    for (int idx = threadIdx.x; idx < 96 * 96; idx += blockDim.x) {
        int k = idx / 96, n = idx - k * 96;
        float w = W[idx];
        uint16_t h = bfbits(w);
        uint16_t l = bfbits(w - bfval(h));
        int p = k >> 1;
        int u = n * AP + (p >> 3) * 8 + permj(p & 7);
        int pos = u * 2 + (k & 1);
        Bh16[pos] = h;
        Bl16[pos] = l;
    }
}

// ---------------- HMMA GEMM + fused alpha ----------------
// CTA: 128 rows x 96 cols, 8 warps as 4(M) x 2(N); warp = 2 m-subtiles of 16 rows.
// B fragments shared across subtiles: 120 LDS.64 per 216 HMMA.
__device__ __forceinline__ void mma16816(float* c, const uint32_t* a, const uint32_t* b) {
    asm volatile(
        "mma.sync.aligned.m16n8k16.row.col.f32.bf16.bf16.f32 "
        "{%0,%1,%2,%3}, {%4,%5,%6,%7}, {%8,%9}, {%0,%1,%2,%3};"
        : "+f"(c[0]), "+f"(c[1]), "+f"(c[2]), "+f"(c[3])
        : "r"(a[0]), "r"(a[1]), "r"(a[2]), "r"(a[3]), "r"(b[0]), "r"(b[1]));
}

static constexpr int OFF_AH = 0;
static constexpr int OFF_AL = OFF_AH + 128 * AP;
static constexpr int OFF_BH = OFF_AL + 128 * AP;
static constexpr int OFF_BL = OFF_BH + 96 * AP;
static constexpr int OFF_AV = OFF_BL + 96 * AP;
static constexpr int OFF_AS = OFF_AV + 192;
static constexpr int OFF_AD = OFF_AS + 128;
static constexpr int SMEM_GEMM = (OFF_AD + 128) * 4;     // ~99.8KB

__global__ void __launch_bounds__(256, 2)
k_gemm_mma(const float* __restrict__ X,
           const uint32_t* __restrict__ Bhg, const uint32_t* __restrict__ Blg,
           const float* __restrict__ avec, float* __restrict__ H) {
    extern __shared__ uint32_t sm4[];
    uint32_t* Ah = sm4 + OFF_AH;
    uint32_t* Al = sm4 + OFF_AL;
    uint32_t* Bh = sm4 + OFF_BH;
    uint32_t* Bl = sm4 + OFF_BL;
    float*    av  = (float*)(sm4 + OFF_AV);
    float*    sAs = (float*)(sm4 + OFF_AS);
    float*    sAd = (float*)(sm4 + OFF_AD);

    int tid = threadIdx.x, warp = tid >> 5, lane = tid & 31;
    int g = lane >> 2, tg = lane & 3;
    int wm = warp >> 1, wn = warp & 1;

    for (int i = tid; i < 192; i += 256) av[i] = avec[i];
    if (tid < 128) { sAs[tid] = 0.f; sAd[tid] = 0.f; }

    // B tile: straight uint4 copy of pre-permuted W
    {
        const uint4* src_h = (const uint4*)Bhg;
        const uint4* src_l = (const uint4*)Blg;
        uint4* dst_h = (uint4*)Bh;
        uint4* dst_l = (uint4*)Bl;
        #pragma unroll
        for (int i = 0; i < 6; i++) {
            int idx = tid + i * 256;
            if (idx < (96 * AP) / 4) {
                dst_h[idx] = src_h[idx];
                dst_l[idx] = src_l[idx];
            }
        }
    }

    // A tile: thread = (row = tid>>1, half = tid&1); 24 pairs each
    {
        int row = tid >> 1, half = tid & 1;
        long gr = (long)blockIdx.x * 128 + row;
        bool valid = gr < NN;
        const float2* xr = (const float2*)(X + gr * 96);
        #pragma unroll
        for (int p = half * 24; p < half * 24 + 24; p++) {
            float2 v = valid ? xr[p] : make_float2(0.f, 0.f);
            uint32_t bx = __float_as_uint(v.x), by = __float_as_uint(v.y);
            uint32_t hpair;
            asm("prmt.b32 %0, %1, %2, 0x7632;" : "=r"(hpair) : "r"(bx), "r"(by));
            float lx = v.x - __uint_as_float(bx & 0xFFFF0000u);
            float ly = v.y - __uint_as_float(by & 0xFFFF0000u);
            uint32_t lpair;
            asm("cvt.rn.bf16x2.f32 %0, %1, %2;" : "=r"(lpair) : "f"(ly), "f"(lx));
            int idx = row * AP + (p >> 3) * 8 + permj(p & 7);
            Ah[idx] = hpair;
            Al[idx] = lpair;
        }
    }
    __syncthreads();

    float c[2][6][4];
    #pragma unroll
    for (int s = 0; s < 2; s++)
        #pragma unroll
        for (int nt = 0; nt < 6; nt++)
            #pragma unroll
            for (int q = 0; q < 4; q++) c[s][nt][q] = 0.f;

    int ra = wm * 32 + g;
    #pragma unroll
    for (int ks = 0; ks < 6; ks++) {
        int ko = ks * 8 + 2 * tg;
        uint2 h00 = *(const uint2*)&Ah[ra * AP + ko];
        uint2 h01 = *(const uint2*)&Ah[(ra + 8) * AP + ko];
        uint2 l00 = *(const uint2*)&Al[ra * AP + ko];
        uint2 l01 = *(const uint2*)&Al[(ra + 8) * AP + ko];
        uint2 h10 = *(const uint2*)&Ah[(ra + 16) * AP + ko];
        uint2 h11 = *(const uint2*)&Ah[(ra + 24) * AP + ko];
        uint2 l10 = *(const uint2*)&Al[(ra + 16) * AP + ko];
        uint2 l11 = *(const uint2*)&Al[(ra + 24) * AP + ko];
        uint32_t ah0[4] = {h00.x, h01.x, h00.y, h01.y};
        uint32_t al0[4] = {l00.x, l01.x, l00.y, l01.y};
        uint32_t ah1[4] = {h10.x, h11.x, h10.y, h11.y};
        uint32_t al1[4] = {l10.x, l11.x, l10.y, l11.y};
        #pragma unroll
        for (int nt = 0; nt < 6; nt++) {
            int col = wn * 48 + nt * 8 + g;
            uint2 bh2 = *(const uint2*)&Bh[col * AP + ko];
            uint2 bl2 = *(const uint2*)&Bl[col * AP + ko];
            uint32_t bh[2] = {bh2.x, bh2.y};
            uint32_t bl[2] = {bl2.x, bl2.y};
            mma16816(c[0][nt], ah0, bh);
            mma16816(c[1][nt], ah1, bh);
            mma16816(c[0][nt], ah0, bl);
            mma16816(c[1][nt], ah1, bl);
            mma16816(c[0][nt], al0, bh);
            mma16816(c[1][nt], al1, bh);
        }
    }

    // alpha partials + H writes per subtile
    #pragma unroll
    for (int s = 0; s < 2; s++) {
        float as0 = 0.f, ad0 = 0.f, as1 = 0.f, ad1 = 0.f;
        #pragma unroll
        for (int nt = 0; nt < 6; nt++) {
            int col = wn * 48 + nt * 8 + tg * 2;
            float a0 = av[col], a1 = av[col + 1];
            float d0 = av[96 + col], d1 = av[97 + col];
            as0 = fmaf(c[s][nt][0], a0, fmaf(c[s][nt][1], a1, as0));
            ad0 = fmaf(c[s][nt][0], d0, fmaf(c[s][nt][1], d1, ad0));
            as1 = fmaf(c[s][nt][2], a0, fmaf(c[s][nt][3], a1, as1));
            ad1 = fmaf(c[s][nt][2], d0, fmaf(c[s][nt][3], d1, ad1));
        }
        #pragma unroll
        for (int o = 1; o <= 2; o <<= 1) {
            as0 += __shfl_xor_sync(0xffffffffu, as0, o);
            ad0 += __shfl_xor_sync(0xffffffffu, ad0, o);
            as1 += __shfl_xor_sync(0xffffffffu, as1, o);
            ad1 += __shfl_xor_sync(0xffffffffu, ad1, o);
        }
        int lr = wm * 32 + s * 16 + g;
        if (tg == 0) {
            atomicAdd(&sAs[lr], as0);
            atomicAdd(&sAd[lr], ad0);
            atomicAdd(&sAs[lr + 8], as1);
            atomicAdd(&sAd[lr + 8], ad1);
        }

        long r0 = (long)blockIdx.x * 128 + lr;
        long r1 = r0 + 8;
        if (r0 < NN) {
            float* o = H + r0 * 96 + wn * 48 + tg * 2;
            #pragma unroll
            for (int nt = 0; nt < 6; nt++)
                *(float2*)(o + nt * 8) = make_float2(c[s][nt][0], c[s][nt][1]);
        }
        if (r1 < NN) {
            float* o = H + r1 * 96 + wn * 48 + tg * 2;
            #pragma unroll
            for (int nt = 0; nt < 6; nt++)
                *(float2*)(o + nt * 8) = make_float2(c[s][nt][2], c[s][nt][3]);
        }
    }

    __syncthreads();
    if (tid < 128) {
        long gr = (long)blockIdx.x * 128 + tid;
        if (gr < NN) {
            g_alpha_s[gr] = sAs[tid];
            g_alpha_d[gr] = sAd[tid];
        }
    }
}

// ---------------- fused edge-weight + aggregation (R12 form, unchanged) ------
__global__ void k_agg(const float* __restrict__ h, float* __restrict__ out, int relu) {
    int t = blockIdx.x * blockDim.x + threadIdx.x;
    int n = t >> 5, lane = t & 31;
    if (n >= NN) return;
    int cnt = g_counts[n];
    if (cnt > ELLW) cnt = ELLW;
    const int* row = g_ell + n * ELLW;
    float asn = g_alpha_s[n];
    bool pay = lane < 24;

    float aw = 0.f;
    float4 acc = make_float4(0.f, 0.f, 0.f, 0.f);

    for (int base = 0; base < cnt; base += 32) {
        int m = cnt - base; if (m > 32) m = 32;
        int dl = 0; float wl = 0.f;
        if (lane < m) {
            dl = row[base + lane];
            float s = asn + g_alpha_d[dl];
            float lr = (s > 0.f) ? s : 0.01f * s;
            wl = __expf(-lr);
        }
        int e = 0;
        for (; e + 1 < m; e += 2) {
            int   d0 = __shfl_sync(0xffffffffu, dl, e);
            int   d1 = __shfl_sync(0xffffffffu, dl, e + 1);
            float w0 = __shfl_sync(0xffffffffu, wl, e);
            float w1 = __shfl_sync(0xffffffffu, wl, e + 1);
            aw += w0 + w1;
            if (pay) {
                const float4* p0 = (const float4*)(h + (size_t)d0 * DD);
                const float4* p1 = (const float4*)(h + (size_t)d1 * DD);
                float4 x0 = p0[lane];
                float4 x1 = p1[lane];
                acc.x = fmaf(w0, x0.x, fmaf(w1, x1.x, acc.x));
                acc.y = fmaf(w0, x0.y, fmaf(w1, x1.y, acc.y));
                acc.z = fmaf(w0, x0.z, fmaf(w1, x1.z, acc.z));
                acc.w = fmaf(w0, x0.w, fmaf(w1, x1.w, acc.w));
            }
        }
        if (e < m) {
            int   d0 = __shfl_sync(0xffffffffu, dl, e);
            float w0 = __shfl_sync(0xffffffffu, wl, e);
            aw += w0;
            if (pay) {
                const float4* p0 = (const float4*)(h + (size_t)d0 * DD);
                float4 x0 = p0[lane];
                acc.x = fmaf(w0, x0.x, acc.x);
                acc.y = fmaf(w0, x0.y, acc.y);
                acc.z = fmaf(w0, x0.z, acc.z);
                acc.w = fmaf(w0, x0.w, acc.w);
            }
        }
    }

    float inv = 1.0f / aw;
    acc.x *= inv; acc.y *= inv; acc.z *= inv; acc.w *= inv;
    if (relu) {
        acc.x = fmaxf(acc.x, 0.f); acc.y = fmaxf(acc.y, 0.f);
        acc.z = fmaxf(acc.z, 0.f); acc.w = fmaxf(acc.w, 0.f);
    }
    if (pay)
        ((float4*)(out + (size_t)n * DD))[lane] = acc;
}

// ---------------- launch ----------------
extern "C" void kernel_launch(void* const* d_in, const int* in_sizes, int n_in,
                              void* d_out, int out_size) {
    const int*   ei = (const int*)d_in[0];
    const float* x  = (const float*)d_in[1];
    const float* W1 = (const float*)d_in[2];
    const float* a1 = (const float*)d_in[3];
    const float* W2 = (const float*)d_in[4];
    const float* a2 = (const float*)d_in[5];
    float* out = (float*)d_out;

    void *ph, *pmid, *pcnt, *pwh, *pwl;
    cudaGetSymbolAddress(&ph, g_h);
    cudaGetSymbolAddress(&pmid, g_mid);
    cudaGetSymbolAddress(&pcnt, g_counts);
    cudaGetSymbolAddress(&pwh, g_wh);
    cudaGetSymbolAddress(&pwl, g_wl);
    float* h   = (float*)ph;
    float* mid = (float*)pmid;
    const uint32_t* wh = (const uint32_t*)pwh;
    const uint32_t* wl = (const uint32_t*)pwl;

    const int TB = 256;
    const int eb = (EE + TB - 1) / TB;
    const int mma_blocks = (NN + 127) / 128;      // 782
    const int warp_blocks = (NN * 32 + TB - 1) / TB;

    cudaFuncSetAttribute(k_gemm_mma, cudaFuncAttributeMaxDynamicSharedMemorySize, SMEM_GEMM);

    // fork: build chain on s2 concurrent with wprep+gemm1 on the captured stream
    cudaStream_t s2;
    cudaStreamCreate(&s2);
    cudaEvent_t evF, evJ;
    cudaEventCreateWithFlags(&evF, cudaEventDisableTiming);
    cudaEventCreateWithFlags(&evJ, cudaEventDisableTiming);

    cudaEventRecord(evF, 0);
    cudaStreamWaitEvent(s2, evF, 0);
    cudaMemsetAsync(pcnt, 0, NN * sizeof(int), s2);
    k_build<<<eb, TB, 0, s2>>>(ei);
    cudaEventRecord(evJ, s2);

    k_wprep<<<2, 256>>>(W1, W2);
    k_gemm_mma<<<mma_blocks, TB, SMEM_GEMM>>>(x, wh, wl, a1, h);

    cudaStreamWaitEvent(0, evJ, 0);     // join before agg needs ELL

    k_agg<<<warp_blocks, TB>>>(h, mid, 0);

    k_gemm_mma<<<mma_blocks, TB, SMEM_GEMM>>>(mid, wh + 96 * AP, wl + 96 * AP, a2, h);
    k_agg<<<warp_blocks, TB>>>(h, out, 1);
}

// round 15
// speedup vs baseline: 1.1433x; 1.1433x over previous
#include <cuda_runtime.h>
#include <cuda_bf16.h>
#include <cstdint>

#define NN 100000
#define EE 800000
#define DD 96
#define ELLW 64
#define AP2 112   // interleaved hi/lo pitch in u32

// ---------------- device scratch (allocation-free) ----------------
__device__ float g_h[NN * DD];
__device__ float g_mid[NN * DD];
__device__ float g_alpha_s[NN];
__device__ float g_alpha_d[NN];
__device__ int   g_ell[NN * ELLW];
__device__ int   g_counts[NN];
__device__ uint32_t g_w[2][96 * AP2];    // pre-permuted W, hi/lo interleaved

__device__ __forceinline__ uint16_t bfbits(float x) {
    __nv_bfloat16 b = __float2bfloat16(x);
    return *reinterpret_cast<uint16_t*>(&b);
}
__device__ __forceinline__ float bfval(uint16_t u) {
    __nv_bfloat16 b = *reinterpret_cast<__nv_bfloat16*>(&u);
    return __bfloat162float(b);
}
// u32 offset (within a row) of the HI word for pair j (0..7) of group grp
__device__ __forceinline__ int ipos(int grp, int j) {
    return grp * 16 + ((j < 4) ? 4 * j : 4 * (j - 4) + 2);
}

// ---------------- ELL build ----------------
__global__ void k_build(const int* __restrict__ ei) {
    __shared__ int s_is64;
    if (threadIdx.x == 0)
        s_is64 = (ei[1] == 0 && ei[3] == 0 && ei[5] == 0) ? 1 : 0;
    __syncthreads();
    int e = blockIdx.x * blockDim.x + threadIdx.x;
    if (e >= EE) return;
    int s, d;
    if (s_is64) { s = ei[2 * e]; d = ei[2 * (EE + e)]; }
    else        { s = ei[e];     d = ei[EE + e]; }
    int slot = atomicAdd(&g_counts[s], 1);
    if (slot < ELLW) g_ell[s * ELLW + slot] = d;
}

// ---------------- W prep: convert + transpose + permute + interleave --------
__global__ void k_wprep(const float* __restrict__ W1, const float* __restrict__ W2) {
    int ly = blockIdx.x;
    const float* W = ly ? W2 : W1;
    uint16_t* B16 = (uint16_t*)g_w[ly];
    for (int idx = threadIdx.x; idx < 96 * 96; idx += blockDim.x) {
        int k = idx / 96, n = idx - k * 96;
        float w = W[idx];
        uint16_t h = bfbits(w);
        uint16_t l = bfbits(w - bfval(h));
        int p = k >> 1;
        int u = n * AP2 + ipos(p >> 3, p & 7);
        B16[u * 2 + (k & 1)] = h;            // hi word
        B16[(u + 1) * 2 + (k & 1)] = l;      // lo word (adjacent u32)
    }
}

// ---------------- HMMA GEMM + fused alpha (R11 structure, LDS.128 frags) ----
__device__ __forceinline__ void mma16816(float* c, const uint32_t* a, const uint32_t* b) {
    asm volatile(
        "mma.sync.aligned.m16n8k16.row.col.f32.bf16.bf16.f32 "
        "{%0,%1,%2,%3}, {%4,%5,%6,%7}, {%8,%9}, {%0,%1,%2,%3};"
        : "+f"(c[0]), "+f"(c[1]), "+f"(c[2]), "+f"(c[3])
        : "r"(a[0]), "r"(a[1]), "r"(a[2]), "r"(a[3]), "r"(b[0]), "r"(b[1]));
}

static constexpr int OFF_A  = 0;                  // 64*112
static constexpr int OFF_B  = OFF_A + 64 * AP2;   // 96*112
static constexpr int OFF_AV = OFF_B + 96 * AP2;
static constexpr int OFF_AS = OFF_AV + 192;
static constexpr int OFF_AD = OFF_AS + 64;
static constexpr int SMEM_GEMM = (OFF_AD + 64) * 4;   // ~73KB

__global__ void __launch_bounds__(256, 3)
k_gemm_mma(const float* __restrict__ X, const uint32_t* __restrict__ Bg,
           const float* __restrict__ avec, float* __restrict__ H) {
    extern __shared__ uint32_t sm4[];
    uint32_t* As = sm4 + OFF_A;
    uint32_t* Bs = sm4 + OFF_B;
    float*    av  = (float*)(sm4 + OFF_AV);
    float*    sAs = (float*)(sm4 + OFF_AS);
    float*    sAd = (float*)(sm4 + OFF_AD);

    int tid = threadIdx.x, warp = tid >> 5, lane = tid & 31;
    int g = lane >> 2, tg = lane & 3;
    int wm = warp >> 1, wn = warp & 1;

    for (int i = tid; i < 192; i += 256) av[i] = avec[i];
    if (tid < 64) { sAs[tid] = 0.f; sAd[tid] = 0.f; }

    // B tile: straight uint4 copy of pre-permuted interleaved W (L2-resident)
    {
        const uint4* src = (const uint4*)Bg;
        uint4* dst = (uint4*)Bs;
        #pragma unroll
        for (int i = 0; i < 11; i++) {
            int idx = tid + i * 256;
            if (idx < (96 * AP2) / 4) dst[idx] = src[idx];
        }
    }

    // A tile: thread = (row = tid>>2, q = tid&3); interleaved STS.64
    {
        int row = tid >> 2, q = tid & 3;
        long gr = (long)blockIdx.x * 64 + row;
        bool valid = gr < NN;
        const float2* xr = (const float2*)(X + gr * 96);
        #pragma unroll
        for (int p = q * 12; p < q * 12 + 12; p++) {
            float2 v = valid ? xr[p] : make_float2(0.f, 0.f);
            uint32_t bx = __float_as_uint(v.x), by = __float_as_uint(v.y);
            uint32_t hpair;
            asm("prmt.b32 %0, %1, %2, 0x7632;" : "=r"(hpair) : "r"(bx), "r"(by));
            float lx = v.x - __uint_as_float(bx & 0xFFFF0000u);
            float ly = v.y - __uint_as_float(by & 0xFFFF0000u);
            uint32_t lpair;
            asm("cvt.rn.bf16x2.f32 %0, %1, %2;" : "=r"(lpair) : "f"(ly), "f"(lx));
            int u = row * AP2 + ipos(p >> 3, p & 7);
            *(uint2*)&As[u] = make_uint2(hpair, lpair);
        }
    }
    __syncthreads();

    float c[6][4];
    #pragma unroll
    for (int nt = 0; nt < 6; nt++)
        #pragma unroll
        for (int q = 0; q < 4; q++) c[nt][q] = 0.f;

    int ra = wm * 16 + g;
    #pragma unroll
    for (int ks = 0; ks < 6; ks++) {
        int ko = ks * 16 + 4 * tg;
        uint4 a0 = *(const uint4*)&As[ra * AP2 + ko];         // hi(tg),lo(tg),hi(tg+4),lo(tg+4)
        uint4 a1 = *(const uint4*)&As[(ra + 8) * AP2 + ko];
        uint32_t ah[4] = {a0.x, a1.x, a0.z, a1.z};
        uint32_t al[4] = {a0.y, a1.y, a0.w, a1.w};
        #pragma unroll
        for (int nt = 0; nt < 6; nt++) {
            int col = wn * 48 + nt * 8 + g;
            uint4 b = *(const uint4*)&Bs[col * AP2 + ko];
            uint32_t bh[2] = {b.x, b.z};
            uint32_t bl[2] = {b.y, b.w};
            mma16816(c[nt], ah, bh);
            mma16816(c[nt], ah, bl);
            mma16816(c[nt], al, bh);
        }
    }

    // alpha partials (this warp's 48 cols)
    float as0 = 0.f, ad0 = 0.f, as1 = 0.f, ad1 = 0.f;
    #pragma unroll
    for (int nt = 0; nt < 6; nt++) {
        int col = wn * 48 + nt * 8 + tg * 2;
        float a0 = av[col], a1 = av[col + 1];
        float d0 = av[96 + col], d1 = av[97 + col];
        as0 = fmaf(c[nt][0], a0, fmaf(c[nt][1], a1, as0));
        ad0 = fmaf(c[nt][0], d0, fmaf(c[nt][1], d1, ad0));
        as1 = fmaf(c[nt][2], a0, fmaf(c[nt][3], a1, as1));
        ad1 = fmaf(c[nt][2], d0, fmaf(c[nt][3], d1, ad1));
    }
    #pragma unroll
    for (int o = 1; o <= 2; o <<= 1) {
        as0 += __shfl_xor_sync(0xffffffffu, as0, o);
        ad0 += __shfl_xor_sync(0xffffffffu, ad0, o);
        as1 += __shfl_xor_sync(0xffffffffu, as1, o);
        ad1 += __shfl_xor_sync(0xffffffffu, ad1, o);
    }
    if (tg == 0) {
        atomicAdd(&sAs[wm * 16 + g], as0);
        atomicAdd(&sAd[wm * 16 + g], ad0);
        atomicAdd(&sAs[wm * 16 + g + 8], as1);
        atomicAdd(&sAd[wm * 16 + g + 8], ad1);
    }

    long r0 = (long)blockIdx.x * 64 + wm * 16 + g;
    long r1 = r0 + 8;
    if (r0 < NN) {
        float* o = H + r0 * 96 + wn * 48 + tg * 2;
        #pragma unroll
        for (int nt = 0; nt < 6; nt++)
            *(float2*)(o + nt * 8) = make_float2(c[nt][0], c[nt][1]);
    }
    if (r1 < NN) {
        float* o = H + r1 * 96 + wn * 48 + tg * 2;
        #pragma unroll
        for (int nt = 0; nt < 6; nt++)
            *(float2*)(o + nt * 8) = make_float2(c[nt][2], c[nt][3]);
    }

    __syncthreads();
    if (tid < 64) {
        long gr = (long)blockIdx.x * 64 + tid;
        if (gr < NN) {
            g_alpha_s[gr] = sAs[tid];
            g_alpha_d[gr] = sAd[tid];
        }
    }
}

// ---------------- fused edge-weight + aggregation (R11/R4 proven form) ------
__global__ void k_agg(const float* __restrict__ h, float* __restrict__ out, int relu) {
    int t = blockIdx.x * blockDim.x + threadIdx.x;
    int n = t >> 5, lane = t & 31;
    if (n >= NN) return;
    int cnt = g_counts[n];
    if (cnt > ELLW) cnt = ELLW;
    const int* row = g_ell + n * ELLW;
    float asn = g_alpha_s[n];

    float aw = 0.f, a0 = 0.f, a1 = 0.f, a2 = 0.f;

    for (int base = 0; base < cnt; base += 32) {
        int m = cnt - base; if (m > 32) m = 32;
        int dl = 0; float wl = 0.f;
        if (lane < m) {
            dl = row[base + lane];
            float s = asn + g_alpha_d[dl];
            float lr = (s > 0.f) ? s : 0.01f * s;
            wl = __expf(-lr);
        }
        int e = 0;
        for (; e + 1 < m; e += 2) {
            int   d0 = __shfl_sync(0xffffffffu, dl, e);
            int   d1 = __shfl_sync(0xffffffffu, dl, e + 1);
            float w0 = __shfl_sync(0xffffffffu, wl, e);
            float w1 = __shfl_sync(0xffffffffu, wl, e + 1);
            const float* h0 = h + (size_t)d0 * DD;
            const float* h1 = h + (size_t)d1 * DD;
            float x00 = h0[lane], x01 = h0[lane + 32], x02 = h0[lane + 64];
            float x10 = h1[lane], x11 = h1[lane + 32], x12 = h1[lane + 64];
            aw += w0 + w1;
            a0 = fmaf(w0, x00, fmaf(w1, x10, a0));
            a1 = fmaf(w0, x01, fmaf(w1, x11, a1));
            a2 = fmaf(w0, x02, fmaf(w1, x12, a2));
        }
        if (e < m) {
            int   d0 = __shfl_sync(0xffffffffu, dl, e);
            float w0 = __shfl_sync(0xffffffffu, wl, e);
            const float* h0 = h + (size_t)d0 * DD;
            aw += w0;
            a0 = fmaf(w0, h0[lane], a0);
            a1 = fmaf(w0, h0[lane + 32], a1);
            a2 = fmaf(w0, h0[lane + 64], a2);
        }
    }

    float inv = 1.0f / aw;
    a0 *= inv; a1 *= inv; a2 *= inv;
    if (relu) { a0 = fmaxf(a0, 0.f); a1 = fmaxf(a1, 0.f); a2 = fmaxf(a2, 0.f); }
    float* o = out + (size_t)n * DD;
    o[lane] = a0; o[lane + 32] = a1; o[lane + 64] = a2;
}

// ---------------- launch ----------------
extern "C" void kernel_launch(void* const* d_in, const int* in_sizes, int n_in,
                              void* d_out, int out_size) {
    const int*   ei = (const int*)d_in[0];
    const float* x  = (const float*)d_in[1];
    const float* W1 = (const float*)d_in[2];
    const float* a1 = (const float*)d_in[3];
    const float* W2 = (const float*)d_in[4];
    const float* a2 = (const float*)d_in[5];
    float* out = (float*)d_out;

    void *ph, *pmid, *pcnt, *pw;
    cudaGetSymbolAddress(&ph, g_h);
    cudaGetSymbolAddress(&pmid, g_mid);
    cudaGetSymbolAddress(&pcnt, g_counts);
    cudaGetSymbolAddress(&pw, g_w);
    float* h   = (float*)ph;
    float* mid = (float*)pmid;
    const uint32_t* w = (const uint32_t*)pw;

    const int TB = 256;
    const int eb = (EE + TB - 1) / TB;
    const int mma_blocks = (NN + 63) / 64;        // 1563
    const int warp_blocks = (NN * 32 + TB - 1) / TB;

    cudaFuncSetAttribute(k_gemm_mma, cudaFuncAttributeMaxDynamicSharedMemorySize, SMEM_GEMM);

    // prep
    cudaMemsetAsync(pcnt, 0, NN * sizeof(int));
    k_wprep<<<2, 256>>>(W1, W2);
    k_build<<<eb, TB>>>(ei);

    // layer 1
    k_gemm_mma<<<mma_blocks, TB, SMEM_GEMM>>>(x, w, a1, h);
    k_agg<<<warp_blocks, TB>>>(h, mid, 0);

    // layer 2
    k_gemm_mma<<<mma_blocks, TB, SMEM_GEMM>>>(mid, w + 96 * AP2, a2, h);
    k_agg<<<warp_blocks, TB>>>(h, out, 1);
}

// round 16
// speedup vs baseline: 1.1831x; 1.0348x over previous
#include <cuda_runtime.h>
#include <cuda_bf16.h>
#include <cstdint>

#define NN 100000
#define EE 800000
#define DD 96
#define ELLW 64
#define AP 56

// ---------------- device scratch (allocation-free) ----------------
__device__ float g_h[NN * DD];
__device__ float g_mid[NN * DD];
__device__ float g_alpha_s[NN];
__device__ float g_alpha_d[NN];
__device__ int   g_ell[NN * ELLW];
__device__ int   g_counts[NN];
__device__ uint32_t g_wh[2][96 * AP];    // pre-permuted W hi (bf16x2)
__device__ uint32_t g_wl[2][96 * AP];    // pre-permuted W lo (bf16x2)

__device__ __forceinline__ uint16_t bfbits(float x) {
    __nv_bfloat16 b = __float2bfloat16(x);
    return *reinterpret_cast<uint16_t*>(&b);
}
__device__ __forceinline__ float bfval(uint16_t u) {
    __nv_bfloat16 b = *reinterpret_cast<__nv_bfloat16*>(&u);
    return __bfloat162float(b);
}
__device__ __forceinline__ int permj(int j) {
    return (j < 4) ? 2 * j : 2 * (j - 4) + 1;
}

// ---------------- ELL build ----------------
__global__ void k_build(const int* __restrict__ ei) {
    __shared__ int s_is64;
    if (threadIdx.x == 0)
        s_is64 = (ei[1] == 0 && ei[3] == 0 && ei[5] == 0) ? 1 : 0;
    __syncthreads();
    int e = blockIdx.x * blockDim.x + threadIdx.x;
    if (e >= EE) return;
    int s, d;
    if (s_is64) { s = ei[2 * e]; d = ei[2 * (EE + e)]; }
    else        { s = ei[e];     d = ei[EE + e]; }
    int slot = atomicAdd(&g_counts[s], 1);
    if (slot < ELLW) g_ell[s * ELLW + slot] = d;
}

// ---------------- W prep ----------------
__global__ void k_wprep(const float* __restrict__ W1, const float* __restrict__ W2) {
    int ly = blockIdx.x;
    const float* W = ly ? W2 : W1;
    uint16_t* Bh16 = (uint16_t*)g_wh[ly];
    uint16_t* Bl16 = (uint16_t*)g_wl[ly];
    for (int idx = threadIdx.x; idx < 96 * 96; idx += blockDim.x) {
        int k = idx / 96, n = idx - k * 96;
        float w = W[idx];
        uint16_t h = bfbits(w);
        uint16_t l = bfbits(w - bfval(h));
        int p = k >> 1;
        int u = n * AP + (p >> 3) * 8 + permj(p & 7);
        int pos = u * 2 + (k & 1);
        Bh16[pos] = h;
        Bl16[pos] = l;
    }
}

// ---------------- HMMA GEMM + fused alpha (R12 proven form) ----------------
__device__ __forceinline__ void mma16816(float* c, const uint32_t* a, const uint32_t* b) {
    asm volatile(
        "mma.sync.aligned.m16n8k16.row.col.f32.bf16.bf16.f32 "
        "{%0,%1,%2,%3}, {%4,%5,%6,%7}, {%8,%9}, {%0,%1,%2,%3};"
        : "+f"(c[0]), "+f"(c[1]), "+f"(c[2]), "+f"(c[3])
        : "r"(a[0]), "r"(a[1]), "r"(a[2]), "r"(a[3]), "r"(b[0]), "r"(b[1]));
}

static constexpr int OFF_AH = 0;
static constexpr int OFF_AL = OFF_AH + 64 * AP;
static constexpr int OFF_BH = OFF_AL + 64 * AP;
static constexpr int OFF_BL = OFF_BH + 96 * AP;
static constexpr int OFF_AV = OFF_BL + 96 * AP;
static constexpr int OFF_AS = OFF_AV + 192;
static constexpr int OFF_AD = OFF_AS + 64;
static constexpr int SMEM_GEMM = (OFF_AD + 64) * 4;

__global__ void __launch_bounds__(256, 3)
k_gemm_mma(const float* __restrict__ X,
           const uint32_t* __restrict__ Bhg, const uint32_t* __restrict__ Blg,
           const float* __restrict__ avec, float* __restrict__ H) {
    extern __shared__ uint32_t sm4[];
    uint32_t* Ah = sm4 + OFF_AH;
    uint32_t* Al = sm4 + OFF_AL;
    uint32_t* Bh = sm4 + OFF_BH;
    uint32_t* Bl = sm4 + OFF_BL;
    float*    av  = (float*)(sm4 + OFF_AV);
    float*    sAs = (float*)(sm4 + OFF_AS);
    float*    sAd = (float*)(sm4 + OFF_AD);

    int tid = threadIdx.x, warp = tid >> 5, lane = tid & 31;
    int g = lane >> 2, tg = lane & 3;
    int wm = warp >> 1, wn = warp & 1;

    for (int i = tid; i < 192; i += 256) av[i] = avec[i];
    if (tid < 64) { sAs[tid] = 0.f; sAd[tid] = 0.f; }

    // B tile: straight uint4 copy of pre-permuted W (L2-resident)
    {
        const uint4* src_h = (const uint4*)Bhg;
        const uint4* src_l = (const uint4*)Blg;
        uint4* dst_h = (uint4*)Bh;
        uint4* dst_l = (uint4*)Bl;
        #pragma unroll
        for (int i = 0; i < 6; i++) {
            int idx = tid + i * 256;
            if (idx < (96 * AP) / 4) {
                dst_h[idx] = src_h[idx];
                dst_l[idx] = src_l[idx];
            }
        }
    }

    // A tile: fast truncation split
    {
        int row = tid >> 2, q = tid & 3;
        long gr = (long)blockIdx.x * 64 + row;
        bool valid = gr < NN;
        const float2* xr = (const float2*)(X + gr * 96);
        #pragma unroll
        for (int p = q * 12; p < q * 12 + 12; p++) {
            float2 v = valid ? xr[p] : make_float2(0.f, 0.f);
            uint32_t bx = __float_as_uint(v.x), by = __float_as_uint(v.y);
            uint32_t hpair;
            asm("prmt.b32 %0, %1, %2, 0x7632;" : "=r"(hpair) : "r"(bx), "r"(by));
            float lx = v.x - __uint_as_float(bx & 0xFFFF0000u);
            float ly = v.y - __uint_as_float(by & 0xFFFF0000u);
            uint32_t lpair;
            asm("cvt.rn.bf16x2.f32 %0, %1, %2;" : "=r"(lpair) : "f"(ly), "f"(lx));
            int idx = row * AP + (p >> 3) * 8 + permj(p & 7);
            Ah[idx] = hpair;
            Al[idx] = lpair;
        }
    }
    __syncthreads();

    float c[6][4];
    #pragma unroll
    for (int nt = 0; nt < 6; nt++)
        #pragma unroll
        for (int q = 0; q < 4; q++) c[nt][q] = 0.f;

    int ra = wm * 16 + g;
    #pragma unroll
    for (int ks = 0; ks < 6; ks++) {
        int ko = ks * 8 + 2 * tg;
        uint2 ah0 = *(const uint2*)&Ah[ra * AP + ko];
        uint2 ah1 = *(const uint2*)&Ah[(ra + 8) * AP + ko];
        uint2 al0 = *(const uint2*)&Al[ra * AP + ko];
        uint2 al1 = *(const uint2*)&Al[(ra + 8) * AP + ko];
        uint32_t ah[4] = {ah0.x, ah1.x, ah0.y, ah1.y};
        uint32_t al[4] = {al0.x, al1.x, al0.y, al1.y};
        #pragma unroll
        for (int nt = 0; nt < 6; nt++) {
            int col = wn * 48 + nt * 8 + g;
            uint2 bh2 = *(const uint2*)&Bh[col * AP + ko];
            uint2 bl2 = *(const uint2*)&Bl[col * AP + ko];
            uint32_t bh[2] = {bh2.x, bh2.y};
            uint32_t bl[2] = {bl2.x, bl2.y};
            mma16816(c[nt], ah, bh);
            mma16816(c[nt], ah, bl);
            mma16816(c[nt], al, bh);
        }
    }

    float as0 = 0.f, ad0 = 0.f, as1 = 0.f, ad1 = 0.f;
    #pragma unroll
    for (int nt = 0; nt < 6; nt++) {
        int col = wn * 48 + nt * 8 + tg * 2;
        float a0 = av[col], a1 = av[col + 1];
        float d0 = av[96 + col], d1 = av[97 + col];
        as0 = fmaf(c[nt][0], a0, fmaf(c[nt][1], a1, as0));
        ad0 = fmaf(c[nt][0], d0, fmaf(c[nt][1], d1, ad0));
        as1 = fmaf(c[nt][2], a0, fmaf(c[nt][3], a1, as1));
        ad1 = fmaf(c[nt][2], d0, fmaf(c[nt][3], d1, ad1));
    }
    #pragma unroll
    for (int o = 1; o <= 2; o <<= 1) {
        as0 += __shfl_xor_sync(0xffffffffu, as0, o);
        ad0 += __shfl_xor_sync(0xffffffffu, ad0, o);
        as1 += __shfl_xor_sync(0xffffffffu, as1, o);
        ad1 += __shfl_xor_sync(0xffffffffu, ad1, o);
    }
    if (tg == 0) {
        atomicAdd(&sAs[wm * 16 + g], as0);
        atomicAdd(&sAd[wm * 16 + g], ad0);
        atomicAdd(&sAs[wm * 16 + g + 8], as1);
        atomicAdd(&sAd[wm * 16 + g + 8], ad1);
    }

    long r0 = (long)blockIdx.x * 64 + wm * 16 + g;
    long r1 = r0 + 8;
    if (r0 < NN) {
        float* o = H + r0 * 96 + wn * 48 + tg * 2;
        #pragma unroll
        for (int nt = 0; nt < 6; nt++)
            *(float2*)(o + nt * 8) = make_float2(c[nt][0], c[nt][1]);
    }
    if (r1 < NN) {
        float* o = H + r1 * 96 + wn * 48 + tg * 2;
        #pragma unroll
        for (int nt = 0; nt < 6; nt++)
            *(float2*)(o + nt * 8) = make_float2(c[nt][2], c[nt][3]);
    }

    __syncthreads();
    if (tid < 64) {
        long gr = (long)blockIdx.x * 64 + tid;
        if (gr < NN) {
            g_alpha_s[gr] = sAs[tid];
            g_alpha_d[gr] = sAd[tid];
        }
    }
}

// ---------------- fused edge-weight + aggregation (R12 proven form) ----------
__global__ void k_agg(const float* __restrict__ h, float* __restrict__ out, int relu) {
    int t = blockIdx.x * blockDim.x + threadIdx.x;
    int n = t >> 5, lane = t & 31;
    if (n >= NN) return;
    int cnt = g_counts[n];
    if (cnt > ELLW) cnt = ELLW;
    const int* row = g_ell + n * ELLW;
    float asn = g_alpha_s[n];
    bool pay = lane < 24;

    float aw = 0.f;
    float4 acc = make_float4(0.f, 0.f, 0.f, 0.f);

    for (int base = 0; base < cnt; base += 32) {
        int m = cnt - base; if (m > 32) m = 32;
        int dl = 0; float wl = 0.f;
        if (lane < m) {
            dl = row[base + lane];
            float s = asn + g_alpha_d[dl];
            float lr = (s > 0.f) ? s : 0.01f * s;
            wl = __expf(-lr);
        }
        int e = 0;
        for (; e + 1 < m; e += 2) {
            int   d0 = __shfl_sync(0xffffffffu, dl, e);
            int   d1 = __shfl_sync(0xffffffffu, dl, e + 1);
            float w0 = __shfl_sync(0xffffffffu, wl, e);
            float w1 = __shfl_sync(0xffffffffu, wl, e + 1);
            aw += w0 + w1;
            if (pay) {
                const float4* p0 = (const float4*)(h + (size_t)d0 * DD);
                const float4* p1 = (const float4*)(h + (size_t)d1 * DD);
                float4 x0 = p0[lane];
                float4 x1 = p1[lane];
                acc.x = fmaf(w0, x0.x, fmaf(w1, x1.x, acc.x));
                acc.y = fmaf(w0, x0.y, fmaf(w1, x1.y, acc.y));
                acc.z = fmaf(w0, x0.z, fmaf(w1, x1.z, acc.z));
                acc.w = fmaf(w0, x0.w, fmaf(w1, x1.w, acc.w));
            }
        }
        if (e < m) {
            int   d0 = __shfl_sync(0xffffffffu, dl, e);
            float w0 = __shfl_sync(0xffffffffu, wl, e);
            aw += w0;
            if (pay) {
                const float4* p0 = (const float4*)(h + (size_t)d0 * DD);
                float4 x0 = p0[lane];
                acc.x = fmaf(w0, x0.x, acc.x);
                acc.y = fmaf(w0, x0.y, acc.y);
                acc.z = fmaf(w0, x0.z, acc.z);
                acc.w = fmaf(w0, x0.w, acc.w);
            }
        }
    }

    float inv = 1.0f / aw;
    acc.x *= inv; acc.y *= inv; acc.z *= inv; acc.w *= inv;
    if (relu) {
        acc.x = fmaxf(acc.x, 0.f); acc.y = fmaxf(acc.y, 0.f);
        acc.z = fmaxf(acc.z, 0.f); acc.w = fmaxf(acc.w, 0.f);
    }
    if (pay)
        ((float4*)(out + (size_t)n * DD))[lane] = acc;
}

// ---------------- launch: fork build chain || wprep+gemm1 -------------------
extern "C" void kernel_launch(void* const* d_in, const int* in_sizes, int n_in,
                              void* d_out, int out_size) {
    const int*   ei = (const int*)d_in[0];
    const float* x  = (const float*)d_in[1];
    const float* W1 = (const float*)d_in[2];
    const float* a1 = (const float*)d_in[3];
    const float* W2 = (const float*)d_in[4];
    const float* a2 = (const float*)d_in[5];
    float* out = (float*)d_out;

    void *ph, *pmid, *pcnt, *pwh, *pwl;
    cudaGetSymbolAddress(&ph, g_h);
    cudaGetSymbolAddress(&pmid, g_mid);
    cudaGetSymbolAddress(&pcnt, g_counts);
    cudaGetSymbolAddress(&pwh, g_wh);
    cudaGetSymbolAddress(&pwl, g_wl);
    float* h   = (float*)ph;
    float* mid = (float*)pmid;
    const uint32_t* wh = (const uint32_t*)pwh;
    const uint32_t* wl = (const uint32_t*)pwl;

    const int TB = 256;
    const int eb = (EE + TB - 1) / TB;
    const int mma_blocks = (NN + 63) / 64;
    const int warp_blocks = (NN * 32 + TB - 1) / TB;

    cudaFuncSetAttribute(k_gemm_mma, cudaFuncAttributeMaxDynamicSharedMemorySize, SMEM_GEMM);

    cudaStream_t s2;
    cudaStreamCreate(&s2);
    cudaEvent_t evF, evJ;
    cudaEventCreateWithFlags(&evF, cudaEventDisableTiming);
    cudaEventCreateWithFlags(&evJ, cudaEventDisableTiming);

    // fork: build chain on s2, concurrent with wprep + gemm1
    cudaEventRecord(evF, 0);
    cudaStreamWaitEvent(s2, evF, 0);
    cudaMemsetAsync(pcnt, 0, NN * sizeof(int), s2);
    k_build<<<eb, TB, 0, s2>>>(ei);
    cudaEventRecord(evJ, s2);

    k_wprep<<<2, 256>>>(W1, W2);
    k_gemm_mma<<<mma_blocks, TB, SMEM_GEMM>>>(x, wh, wl, a1, h);

    cudaStreamWaitEvent(0, evJ, 0);     // join: agg1 needs the ELL table

    k_agg<<<warp_blocks, TB>>>(h, mid, 0);
    k_gemm_mma<<<mma_blocks, TB, SMEM_GEMM>>>(mid, wh + 96 * AP, wl + 96 * AP, a2, h);
    k_agg<<<warp_blocks, TB>>>(h, out, 1);
}